// round 13
// baseline (speedup 1.0000x reference)
#include <cuda_runtime.h>
#include <cuda_bf16.h>
#include <cstdint>

// ---------------- problem constants ----------------
#define NF 128
#define NGRAPHS 10000
#define MAXM 500000
#define EPSBN 1e-5f
#define BM 64                       // rows per tile

// ---------------- scratch globals (no allocs allowed) ----------------
__device__ float g_S[NGRAPHS * NF];
__device__ float g_P[NGRAPHS * NF];
__device__ float g_H1[(size_t)MAXM * NF];
__device__ float g_stat0[2 * NF];
__device__ float g_sc0[NF], g_sh0[NF];
__device__ float g_stat1[2 * NF];
__device__ float g_sc1[NF], g_sh1[NF];
__device__ unsigned g_sync0, g_sync1;
// weight tiles, bf16 hi/lo, layout [k][n] pitch 136 bf16 (272B/row), 34816B each
__device__ uint4 g_wlhi[2176], g_wllo[2176];
__device__ uint4 g_w1hi[2176], g_w1lo[2176], g_w2hi[2176], g_w2lo[2176];

// ---------------- smem layout ----------------
// x stage 32768 | T stage 32768 | A hi 17408 | A lo 17408 | params 1536
#define OFF_STAGE  0
#define OFF_STAGET 32768
#define OFF_AHI    65536
#define OFF_ALO    (65536 + 17408)
#define OFF_PRM    (65536 + 34816)
#define SMEM_MMA   (OFF_PRM + 3 * 512)   // 101,888 B -> 2 CTAs/SM

// ---------------- ptx helpers (sm_80-level only; no tcgen05!) ----------------
__device__ __forceinline__ void ldsm_x4(uint32_t* r, uint32_t addr) {
    asm volatile("ldmatrix.sync.aligned.m8n8.x4.shared.b16 {%0,%1,%2,%3}, [%4];"
                 : "=r"(r[0]), "=r"(r[1]), "=r"(r[2]), "=r"(r[3]) : "r"(addr));
}
__device__ __forceinline__ void ldsm_x4_t(uint32_t* r, uint32_t addr) {
    asm volatile("ldmatrix.sync.aligned.m8n8.x4.trans.shared.b16 {%0,%1,%2,%3}, [%4];"
                 : "=r"(r[0]), "=r"(r[1]), "=r"(r[2]), "=r"(r[3]) : "r"(addr));
}
__device__ __forceinline__ void mma_bf16(float* c, const uint32_t* a, const uint32_t* b) {
    asm volatile("mma.sync.aligned.m16n8k16.row.col.f32.bf16.bf16.f32 "
                 "{%0,%1,%2,%3}, {%4,%5,%6,%7}, {%8,%9}, {%0,%1,%2,%3};"
                 : "+f"(c[0]), "+f"(c[1]), "+f"(c[2]), "+f"(c[3])
                 : "r"(a[0]), "r"(a[1]), "r"(a[2]), "r"(a[3]), "r"(b[0]), "r"(b[1]));
}
__device__ __forceinline__ void cp16(uint32_t dst, const void* src, int sz) {
    asm volatile("cp.async.cg.shared.global [%0], [%1], 16, %2;"
                 :: "r"(dst), "l"(src), "r"(sz));
}
#define CP_COMMIT() asm volatile("cp.async.commit_group;")
#define CP_WAIT0()  asm volatile("cp.async.wait_group 0;")

// fast split: hi = truncated top-16 bits (PRMT pack), lo = rn-bf16 of residual
__device__ __forceinline__ void split4(float4 v, uint2& hi, uint2& lo) {
    uint32_t u0 = __float_as_uint(v.x), u1 = __float_as_uint(v.y),
             u2 = __float_as_uint(v.z), u3 = __float_as_uint(v.w);
    asm("prmt.b32 %0, %1, %2, 0x7632;" : "=r"(hi.x) : "r"(u0), "r"(u1));
    asm("prmt.b32 %0, %1, %2, 0x7632;" : "=r"(hi.y) : "r"(u2), "r"(u3));
    float l0 = v.x - __uint_as_float(u0 & 0xFFFF0000u);
    float l1 = v.y - __uint_as_float(u1 & 0xFFFF0000u);
    float l2 = v.z - __uint_as_float(u2 & 0xFFFF0000u);
    float l3 = v.w - __uint_as_float(u3 & 0xFFFF0000u);
    asm("cvt.rn.bf16x2.f32 %0, %1, %2;" : "=r"(lo.x) : "f"(l1), "f"(l0));
    asm("cvt.rn.bf16x2.f32 %0, %1, %2;" : "=r"(lo.y) : "f"(l3), "f"(l2));
}

// ---------------- init ----------------
__global__ void init_kernel(const float* __restrict__ WL,
                            const float* __restrict__ W1,
                            const float* __restrict__ W2) {
    const int gtid = blockIdx.x * 256 + threadIdx.x;
    const int n1 = NGRAPHS * NF;
    for (int i = gtid; i < n1; i += gridDim.x * 256) g_S[i] = 0.f;
    if (gtid < 2 * NF) { g_stat0[gtid] = 0.f; g_stat1[gtid] = 0.f; }
    if (gtid == 0) { g_sync0 = 0u; g_sync1 = 0u; }
    if (gtid < NF * NF) {
        int k = gtid >> 7, n = gtid & 127;
        uint32_t off = (uint32_t)k * 272 + (uint32_t)n * 2;
        float v; __nv_bfloat16 h, l;
        v = WL[gtid]; h = __float2bfloat16(v); l = __float2bfloat16(v - __bfloat162float(h));
        *(unsigned short*)((unsigned char*)g_wlhi + off) = __bfloat16_as_ushort(h);
        *(unsigned short*)((unsigned char*)g_wllo + off) = __bfloat16_as_ushort(l);
        v = W1[gtid]; h = __float2bfloat16(v); l = __float2bfloat16(v - __bfloat162float(h));
        *(unsigned short*)((unsigned char*)g_w1hi + off) = __bfloat16_as_ushort(h);
        *(unsigned short*)((unsigned char*)g_w1lo + off) = __bfloat16_as_ushort(l);
        v = W2[gtid]; h = __float2bfloat16(v); l = __float2bfloat16(v - __bfloat162float(h));
        *(unsigned short*)((unsigned char*)g_w2hi + off) = __bfloat16_as_ushort(h);
        *(unsigned short*)((unsigned char*)g_w2lo + off) = __bfloat16_as_ushort(l);
    }
}

// float4 lanes: 32 threads/row, 4 row-lanes, run-length accumulate per lane
__global__ void seg_sum_kernel(const float* __restrict__ x,
                               const int* __restrict__ batch, int M) {
    const int rg = threadIdx.x >> 5;
    const int c4 = threadIdx.x & 31;
    int r0 = blockIdx.x * 256;
    int rend = min(r0 + 256, M);
    float4 acc = make_float4(0.f, 0.f, 0.f, 0.f);
    int cur = -1;
    for (int r = r0 + rg; r < rend; r += 4) {
        int b = __ldg(&batch[r]);
        if (b != cur) {
            if (cur >= 0) {
                float* d = &g_S[(size_t)cur * NF + c4 * 4];
                atomicAdd(d + 0, acc.x); atomicAdd(d + 1, acc.y);
                atomicAdd(d + 2, acc.z); atomicAdd(d + 3, acc.w);
            }
            acc = make_float4(0.f, 0.f, 0.f, 0.f); cur = b;
        }
        float4 v = __ldg((const float4*)x + (size_t)r * 32 + c4);
        acc.x += v.x; acc.y += v.y; acc.z += v.z; acc.w += v.w;
    }
    if (cur >= 0) {
        float* d = &g_S[(size_t)cur * NF + c4 * 4];
        atomicAdd(d + 0, acc.x); atomicAdd(d + 1, acc.y);
        atomicAdd(d + 2, acc.z); atomicAdd(d + 3, acc.w);
    }
}

// ---------------- persistent HMMA GEMM, BM=64, 128 thr, 2 CTAs/SM ----------------
// 4 warps, 1(m)x4(n) grid, warp tile 64x32.  W in registers.  x AND gathered-T
// tiles staged via cp.async one full MMA phase ahead.
// MODE 0: C = Asrc @ W                                  (+ BN0 stats + bn-prep tail)
// MODE 1: C = (x + relu(P[batch]*sc+sh)) @ W + bias     (+ BN1 stats + bn-prep tail)
// MODE 2: C = relu(Asrc*sc + sh) @ W + bias
template <int MODE>
__global__ void __launch_bounds__(128, 2)
gemm_mma(const float* __restrict__ Asrc,
         const uint4* __restrict__ Whi_g, const uint4* __restrict__ Wlo_g,
         const float* __restrict__ bias,
         const float* __restrict__ Tm, const int* __restrict__ batch,
         const float* __restrict__ sc, const float* __restrict__ sh,
         float* __restrict__ C, float* __restrict__ stats,
         const float* __restrict__ gamma, const float* __restrict__ beta,
         float nrows, float* __restrict__ sc_out, float* __restrict__ sh_out,
         unsigned* __restrict__ sync_ctr, int M, int ntiles) {
    constexpr bool STATS = (MODE != 2);
    constexpr bool HASBIAS = (MODE != 0);

    extern __shared__ unsigned char sm[];
    float* psm = (float*)(sm + OFF_PRM);     // sc @128, sh @256 (floats)
    const float4* stage  = (const float4*)(sm + OFF_STAGE);
    const float4* stageT = (const float4*)(sm + OFF_STAGET);
    const uint32_t sb = (uint32_t)__cvta_generic_to_shared(sm);

    const int tid = threadIdx.x;
    const int wid = tid >> 5, lane = tid & 31;
    const int tig = lane & 3, grp = lane >> 2;
    const int warp_n = wid;                    // 1x4 grid: warp owns 32-col strip
    const int lrow = lane & 15, lsel = lane >> 4;

    if (MODE != 0 && tid < NF) {
        psm[128 + tid] = __ldg(&sc[tid]);
        psm[256 + tid] = __ldg(&sh[tid]);
    }

    // ---- stage W through the A region, hoist fragments into registers ----
    uint32_t wh[8][2][4], wl[8][2][4];
    {
        uint4* dst = (uint4*)(sm + OFF_AHI);
        for (int i = tid; i < 2176; i += 128) dst[i] = __ldg(&Whi_g[i]);
        __syncthreads();
#pragma unroll
        for (int kt = 0; kt < 8; ++kt)
#pragma unroll
            for (int nb = 0; nb < 2; ++nb) {
                uint32_t a = sb + OFF_AHI + (uint32_t)(kt * 16 + lrow) * 272
                           + (uint32_t)(warp_n * 32 + nb * 16 + lsel * 8) * 2;
                ldsm_x4_t(wh[kt][nb], a);
            }
        __syncthreads();
        for (int i = tid; i < 2176; i += 128) dst[i] = __ldg(&Wlo_g[i]);
        __syncthreads();
#pragma unroll
        for (int kt = 0; kt < 8; ++kt)
#pragma unroll
            for (int nb = 0; nb < 2; ++nb) {
                uint32_t a = sb + OFF_AHI + (uint32_t)(kt * 16 + lrow) * 272
                           + (uint32_t)(warp_n * 32 + nb * 16 + lsel * 8) * 2;
                ldsm_x4_t(wl[kt][nb], a);
            }
        __syncthreads();
    }

    // per-lane BN params for convert (lane <-> float4 column fixed)
    float4 sc4 = make_float4(0.f, 0.f, 0.f, 0.f), sh4 = sc4;
    if (MODE != 0) {
        sc4 = ((const float4*)(psm + 128))[lane];
        sh4 = ((const float4*)(psm + 256))[lane];
    }

    float bias_r[4][2];
#pragma unroll
    for (int nt = 0; nt < 4; ++nt) {
        bias_r[nt][0] = HASBIAS ? __ldg(&bias[warp_n * 32 + nt * 8 + tig * 2]) : 0.f;
        bias_r[nt][1] = HASBIAS ? __ldg(&bias[warp_n * 32 + nt * 8 + tig * 2 + 1]) : 0.f;
    }

    float cs[4][2], cq[4][2];
    if (STATS) {
#pragma unroll
        for (int nt = 0; nt < 4; ++nt) { cs[nt][0] = cs[nt][1] = 0.f; cq[nt][0] = cq[nt][1] = 0.f; }
    }

    unsigned char* Ah = sm + OFF_AHI;
    unsigned char* Al = sm + OFF_ALO;

    // stage filler: x tile (+ gathered T tile for MODE 1) for tile `t`
    auto stage_fill = [&](int t) {
#pragma unroll
        for (int i = 0; i < 16; ++i) {
            int idx = tid + 128 * i;
            int r = idx >> 5, q = idx & 31;
            int rg = t * BM + r;
            int rc = min(rg, M - 1);
            cp16(sb + OFF_STAGE + (uint32_t)(r * 32 + q) * 16,
                 (const float4*)Asrc + (size_t)rc * 32 + q, rg < M ? 16 : 0);
            if (MODE == 1) {
                int g = __ldg(&batch[rc]);
                cp16(sb + OFF_STAGET + (uint32_t)(r * 32 + q) * 16,
                     (const float4*)Tm + (size_t)g * 32 + q, rg < M ? 16 : 0);
            }
        }
    };

    // ---- prologue: stage first tile ----
    if (blockIdx.x < ntiles) stage_fill(blockIdx.x);
    CP_COMMIT();

    for (int tile = blockIdx.x; tile < ntiles; tile += gridDim.x) {
        CP_WAIT0();
        __syncthreads();   // stage ready; previous mainloop reads of A complete

        // ---- convert (pure smem): warp rows [wid*16, wid*16+16) ----
        {
            int crow0 = wid * 16;
#pragma unroll
            for (int i = 0; i < 16; ++i) {
                int crow = crow0 + i;
                int rg = tile * BM + crow;
                bool valid = rg < M;
                float4 v = stage[crow * 32 + lane];
                if (MODE == 1) {
                    float4 t = stageT[crow * 32 + lane];
                    v.x += fmaxf(fmaf(t.x, sc4.x, sh4.x), 0.f);
                    v.y += fmaxf(fmaf(t.y, sc4.y, sh4.y), 0.f);
                    v.z += fmaxf(fmaf(t.z, sc4.z, sh4.z), 0.f);
                    v.w += fmaxf(fmaf(t.w, sc4.w, sh4.w), 0.f);
                } else if (MODE == 2) {
                    v.x = fmaxf(fmaf(v.x, sc4.x, sh4.x), 0.f);
                    v.y = fmaxf(fmaf(v.y, sc4.y, sh4.y), 0.f);
                    v.z = fmaxf(fmaf(v.z, sc4.z, sh4.z), 0.f);
                    v.w = fmaxf(fmaf(v.w, sc4.w, sh4.w), 0.f);
                }
                if (!valid) v = make_float4(0.f, 0.f, 0.f, 0.f);
                uint2 hi, lo;
                split4(v, hi, lo);
                uint32_t off = (uint32_t)crow * 272 + (uint32_t)lane * 8;
                *(uint2*)(Ah + off) = hi;
                *(uint2*)(Al + off) = lo;
            }
        }
        __syncthreads();   // A ready; stages consumed -> safe to refill

        // ---- prefetch next tile into stages (overlaps with mainloop) ----
        {
            int nxt = tile + gridDim.x;
            if (nxt < ntiles) stage_fill(nxt);
            CP_COMMIT();
        }

        // ---- HMMA mainloop: 3-chain bf16 split, 64x32 microtile/warp, W in regs ----
        float acc[4][4][4];
#pragma unroll
        for (int mt = 0; mt < 4; ++mt)
#pragma unroll
            for (int nt = 0; nt < 4; ++nt)
#pragma unroll
                for (int e = 0; e < 4; ++e) acc[mt][nt][e] = 0.f;

#pragma unroll
        for (int kt = 0; kt < 8; ++kt) {
            const int k0 = kt * 16;
            uint32_t ahi[4][4], alo[4][4];
#pragma unroll
            for (int mt = 0; mt < 4; ++mt) {
                int r = mt * 16 + lrow;
                uint32_t a = sb + OFF_AHI + (uint32_t)r * 272 + (uint32_t)(k0 + lsel * 8) * 2;
                ldsm_x4(ahi[mt], a);
                ldsm_x4(alo[mt], a + (OFF_ALO - OFF_AHI));
            }
#pragma unroll
            for (int mt = 0; mt < 4; ++mt)
#pragma unroll
                for (int nt = 0; nt < 4; ++nt) {
                    const uint32_t* bh = &wh[kt][nt >> 1][(nt & 1) * 2];
                    const uint32_t* bl = &wl[kt][nt >> 1][(nt & 1) * 2];
                    mma_bf16(acc[mt][nt], ahi[mt], bh);
                    mma_bf16(acc[mt][nt], ahi[mt], bl);
                    mma_bf16(acc[mt][nt], alo[mt], bh);
                }
        }

        // ---- epilogue: bias, store, fused stats ----
#pragma unroll
        for (int mt = 0; mt < 4; ++mt) {
            int r0 = tile * BM + mt * 16 + grp;
            int r1 = r0 + 8;
            bool v0 = r0 < M, v1 = r1 < M;
            float* p0 = C + (size_t)r0 * NF + warp_n * 32 + tig * 2;
            float* p1 = C + (size_t)r1 * NF + warp_n * 32 + tig * 2;
#pragma unroll
            for (int nt = 0; nt < 4; ++nt) {
                float c0 = acc[mt][nt][0] + bias_r[nt][0];
                float c1 = acc[mt][nt][1] + bias_r[nt][1];
                float c2 = acc[mt][nt][2] + bias_r[nt][0];
                float c3 = acc[mt][nt][3] + bias_r[nt][1];
                if (v0) {
                    *(float2*)(p0 + nt * 8) = make_float2(c0, c1);
                    if (STATS) { cs[nt][0] += c0; cs[nt][1] += c1; cq[nt][0] += c0 * c0; cq[nt][1] += c1 * c1; }
                }
                if (v1) {
                    *(float2*)(p1 + nt * 8) = make_float2(c2, c3);
                    if (STATS) { cs[nt][0] += c2; cs[nt][1] += c3; cq[nt][0] += c2 * c2; cq[nt][1] += c3 * c3; }
                }
            }
        }
    }

    // ---- stats flush + last-block bn-prep ----
    if (STATS) {
        CP_WAIT0();
        __syncthreads();
        float* cs_sm = (float*)(sm + OFF_AHI);     // [128]
        float* cq_sm = cs_sm + 128;
#pragma unroll
        for (int nt = 0; nt < 4; ++nt)
#pragma unroll
            for (int par = 0; par < 2; ++par) {
                float s = cs[nt][par], q = cq[nt][par];
#pragma unroll
                for (int msk = 16; msk >= 4; msk >>= 1) {
                    s += __shfl_xor_sync(0xFFFFFFFFu, s, msk);
                    q += __shfl_xor_sync(0xFFFFFFFFu, q, msk);
                }
                if (lane < 4) {
                    int col = warp_n * 32 + nt * 8 + tig * 2 + par;
                    cs_sm[col] = s;
                    cq_sm[col] = q;
                }
            }
        __syncthreads();
        atomicAdd(&stats[tid],      cs_sm[tid]);
        atomicAdd(&stats[NF + tid], cq_sm[tid]);

        __shared__ unsigned last_f;
        __threadfence();
        __syncthreads();
        if (tid == 0) last_f = (atomicAdd(sync_ctr, 1u) == (unsigned)(gridDim.x - 1)) ? 1u : 0u;
        __syncthreads();
        if (last_f) {
            float su = atomicAdd(&stats[tid], 0.f);
            float sq = atomicAdd(&stats[NF + tid], 0.f);
            float mu = su / nrows;
            float var = sq / nrows - mu * mu;
            float s = rsqrtf(var + EPSBN) * __ldg(&gamma[tid]);
            sc_out[tid] = s;
            sh_out[tid] = __ldg(&beta[tid]) - mu * s;
        }
    }
}

// ---------------- launcher ----------------
extern "C" void kernel_launch(void* const* d_in, const int* in_sizes, int n_in,
                              void* d_out, int out_size) {
    const float* x     = (const float*)d_in[0];
    const int*   batch = (const int*)d_in[3];
    const float* W_lin = (const float*)d_in[4];
    const float* bn_g  = (const float*)d_in[5];
    const float* bn_b  = (const float*)d_in[6];
    const float* W1    = (const float*)d_in[7];
    const float* b1    = (const float*)d_in[8];
    const float* bn1_g = (const float*)d_in[9];
    const float* bn1_b = (const float*)d_in[10];
    const float* W2    = (const float*)d_in[11];
    const float* b2    = (const float*)d_in[12];
    float*       out   = (float*)d_out;

    const int M = in_sizes[0] / NF;   // 500000
    const int ntiles_big = (M + BM - 1) / BM;
    const int ntiles_sml = (NGRAPHS + BM - 1) / BM;   // 157

    float *pS, *pP, *pH1, *pstat0, *psc0, *psh0, *pstat1, *psc1, *psh1;
    cudaGetSymbolAddress((void**)&pS, g_S);
    cudaGetSymbolAddress((void**)&pP, g_P);
    cudaGetSymbolAddress((void**)&pH1, g_H1);
    cudaGetSymbolAddress((void**)&pstat0, g_stat0);
    cudaGetSymbolAddress((void**)&psc0, g_sc0);
    cudaGetSymbolAddress((void**)&psh0, g_sh0);
    cudaGetSymbolAddress((void**)&pstat1, g_stat1);
    cudaGetSymbolAddress((void**)&psc1, g_sc1);
    cudaGetSymbolAddress((void**)&psh1, g_sh1);
    unsigned *psync0, *psync1;
    cudaGetSymbolAddress((void**)&psync0, g_sync0);
    cudaGetSymbolAddress((void**)&psync1, g_sync1);
    uint4 *pwlh, *pwll, *pw1h, *pw1l, *pw2h, *pw2l;
    cudaGetSymbolAddress((void**)&pwlh, g_wlhi);
    cudaGetSymbolAddress((void**)&pwll, g_wllo);
    cudaGetSymbolAddress((void**)&pw1h, g_w1hi);
    cudaGetSymbolAddress((void**)&pw1l, g_w1lo);
    cudaGetSymbolAddress((void**)&pw2h, g_w2hi);
    cudaGetSymbolAddress((void**)&pw2l, g_w2lo);

    int dev = 0, nsm = 148;
    cudaGetDevice(&dev);
    cudaDeviceGetAttribute(&nsm, cudaDevAttrMultiProcessorCount, dev);
    const int grid_big = 2 * nsm;
    const int grid_sml = (grid_big < ntiles_sml) ? grid_big : ntiles_sml;

    cudaFuncSetAttribute(gemm_mma<0>, cudaFuncAttributeMaxDynamicSharedMemorySize, SMEM_MMA);
    cudaFuncSetAttribute(gemm_mma<1>, cudaFuncAttributeMaxDynamicSharedMemorySize, SMEM_MMA);
    cudaFuncSetAttribute(gemm_mma<2>, cudaFuncAttributeMaxDynamicSharedMemorySize, SMEM_MMA);

    // (1) init
    init_kernel<<<2500, 256>>>(W_lin, W1, W2);
    // (2) segment sum
    seg_sum_kernel<<<(M + 255) / 256, 128>>>(x, batch, M);
    // (3) P = S @ W_lin  (+ BN0 stats + bn-prep tail)
    gemm_mma<0><<<grid_sml, 128, SMEM_MMA>>>(pS, pwlh, pwll, nullptr, nullptr, nullptr,
                                             nullptr, nullptr, pP, pstat0,
                                             bn_g, bn_b, (float)NGRAPHS, psc0, psh0,
                                             psync0, NGRAPHS, ntiles_sml);
    // (4) H1 = (x + relu(BN0(P))[batch]) @ W1 + b1  (+ BN1 stats + bn-prep tail)
    gemm_mma<1><<<grid_big, 128, SMEM_MMA>>>(x, pw1h, pw1l, b1, pP, batch,
                                             psc0, psh0, pH1, pstat1,
                                             bn1_g, bn1_b, (float)M, psc1, psh1,
                                             psync1, M, ntiles_big);
    // (5) out = relu(BN1(H1)) @ W2 + b2
    gemm_mma<2><<<grid_big, 128, SMEM_MMA>>>(pH1, pw2h, pw2l, b2, nullptr, nullptr,
                                             psc1, psh1, out, nullptr,
                                             nullptr, nullptr, 0.f, nullptr, nullptr,
                                             nullptr, M, ntiles_big);
}

// round 14
// speedup vs baseline: 1.4516x; 1.4516x over previous
#include <cuda_runtime.h>
#include <cuda_bf16.h>
#include <cstdint>

// ---------------- problem constants ----------------
#define NF 128
#define NGRAPHS 10000
#define MAXM 500000
#define EPSBN 1e-5f
#define BM 64                       // rows per tile

// ---------------- scratch globals (no allocs allowed) ----------------
__device__ float g_S[NGRAPHS * NF];
__device__ float g_P[NGRAPHS * NF];
__device__ float g_H1[(size_t)MAXM * NF];
__device__ float g_stat0[2 * NF];
__device__ float g_sc0[NF], g_sh0[NF];
__device__ float g_stat1[2 * NF];
__device__ float g_sc1[NF], g_sh1[NF];
__device__ unsigned g_sync0, g_sync1;
// weight tiles, bf16 hi/lo, layout [k][n] pitch 136 bf16 (272B/row), 34816B each
__device__ uint4 g_wlhi[2176], g_wllo[2176];
__device__ uint4 g_w1hi[2176], g_w1lo[2176], g_w2hi[2176], g_w2lo[2176];

// ---------------- smem layout ----------------
// x stage 32768 | T stage 32768 | A hi 17408 | A lo 17408 | params 1536 | bidx 512
#define OFF_STAGE  0
#define OFF_STAGET 32768
#define OFF_AHI    65536
#define OFF_ALO    (65536 + 17408)
#define OFF_PRM    (65536 + 34816)
#define OFF_BIDX   (OFF_PRM + 3 * 512)
#define SMEM_MMA   (OFF_BIDX + 512)     // 102,400 B -> 2 CTAs/SM

// ---------------- ptx helpers (sm_80-level only; no tcgen05!) ----------------
__device__ __forceinline__ void ldsm_x4(uint32_t* r, uint32_t addr) {
    asm volatile("ldmatrix.sync.aligned.m8n8.x4.shared.b16 {%0,%1,%2,%3}, [%4];"
                 : "=r"(r[0]), "=r"(r[1]), "=r"(r[2]), "=r"(r[3]) : "r"(addr));
}
__device__ __forceinline__ void ldsm_x4_t(uint32_t* r, uint32_t addr) {
    asm volatile("ldmatrix.sync.aligned.m8n8.x4.trans.shared.b16 {%0,%1,%2,%3}, [%4];"
                 : "=r"(r[0]), "=r"(r[1]), "=r"(r[2]), "=r"(r[3]) : "r"(addr));
}
__device__ __forceinline__ void mma_bf16(float* c, const uint32_t* a, const uint32_t* b) {
    asm volatile("mma.sync.aligned.m16n8k16.row.col.f32.bf16.bf16.f32 "
                 "{%0,%1,%2,%3}, {%4,%5,%6,%7}, {%8,%9}, {%0,%1,%2,%3};"
                 : "+f"(c[0]), "+f"(c[1]), "+f"(c[2]), "+f"(c[3])
                 : "r"(a[0]), "r"(a[1]), "r"(a[2]), "r"(a[3]), "r"(b[0]), "r"(b[1]));
}
__device__ __forceinline__ void cp16(uint32_t dst, const void* src, int sz) {
    asm volatile("cp.async.cg.shared.global [%0], [%1], 16, %2;"
                 :: "r"(dst), "l"(src), "r"(sz));
}
#define CP_COMMIT() asm volatile("cp.async.commit_group;")
#define CP_WAIT0()  asm volatile("cp.async.wait_group 0;")

// fast split: hi = truncated top-16 bits (PRMT pack), lo = rn-bf16 of residual
__device__ __forceinline__ void split4(float4 v, uint2& hi, uint2& lo) {
    uint32_t u0 = __float_as_uint(v.x), u1 = __float_as_uint(v.y),
             u2 = __float_as_uint(v.z), u3 = __float_as_uint(v.w);
    asm("prmt.b32 %0, %1, %2, 0x7632;" : "=r"(hi.x) : "r"(u0), "r"(u1));
    asm("prmt.b32 %0, %1, %2, 0x7632;" : "=r"(hi.y) : "r"(u2), "r"(u3));
    float l0 = v.x - __uint_as_float(u0 & 0xFFFF0000u);
    float l1 = v.y - __uint_as_float(u1 & 0xFFFF0000u);
    float l2 = v.z - __uint_as_float(u2 & 0xFFFF0000u);
    float l3 = v.w - __uint_as_float(u3 & 0xFFFF0000u);
    asm("cvt.rn.bf16x2.f32 %0, %1, %2;" : "=r"(lo.x) : "f"(l1), "f"(l0));
    asm("cvt.rn.bf16x2.f32 %0, %1, %2;" : "=r"(lo.y) : "f"(l3), "f"(l2));
}

// ---------------- init ----------------
__global__ void init_kernel(const float* __restrict__ WL,
                            const float* __restrict__ W1,
                            const float* __restrict__ W2) {
    const int gtid = blockIdx.x * 256 + threadIdx.x;
    const int n1 = NGRAPHS * NF;
    for (int i = gtid; i < n1; i += gridDim.x * 256) g_S[i] = 0.f;
    if (gtid < 2 * NF) { g_stat0[gtid] = 0.f; g_stat1[gtid] = 0.f; }
    if (gtid == 0) { g_sync0 = 0u; g_sync1 = 0u; }
    if (gtid < NF * NF) {
        int k = gtid >> 7, n = gtid & 127;
        uint32_t off = (uint32_t)k * 272 + (uint32_t)n * 2;
        float v; __nv_bfloat16 h, l;
        v = WL[gtid]; h = __float2bfloat16(v); l = __float2bfloat16(v - __bfloat162float(h));
        *(unsigned short*)((unsigned char*)g_wlhi + off) = __bfloat16_as_ushort(h);
        *(unsigned short*)((unsigned char*)g_wllo + off) = __bfloat16_as_ushort(l);
        v = W1[gtid]; h = __float2bfloat16(v); l = __float2bfloat16(v - __bfloat162float(h));
        *(unsigned short*)((unsigned char*)g_w1hi + off) = __bfloat16_as_ushort(h);
        *(unsigned short*)((unsigned char*)g_w1lo + off) = __bfloat16_as_ushort(l);
        v = W2[gtid]; h = __float2bfloat16(v); l = __float2bfloat16(v - __bfloat162float(h));
        *(unsigned short*)((unsigned char*)g_w2hi + off) = __bfloat16_as_ushort(h);
        *(unsigned short*)((unsigned char*)g_w2lo + off) = __bfloat16_as_ushort(l);
    }
}

// float4 lanes: 32 threads/row, 4 row-lanes, run-length accumulate per lane
__global__ void seg_sum_kernel(const float* __restrict__ x,
                               const int* __restrict__ batch, int M) {
    const int rg = threadIdx.x >> 5;
    const int c4 = threadIdx.x & 31;
    int r0 = blockIdx.x * 256;
    int rend = min(r0 + 256, M);
    float4 acc = make_float4(0.f, 0.f, 0.f, 0.f);
    int cur = -1;
    for (int r = r0 + rg; r < rend; r += 4) {
        int b = __ldg(&batch[r]);
        if (b != cur) {
            if (cur >= 0) {
                float* d = &g_S[(size_t)cur * NF + c4 * 4];
                atomicAdd(d + 0, acc.x); atomicAdd(d + 1, acc.y);
                atomicAdd(d + 2, acc.z); atomicAdd(d + 3, acc.w);
            }
            acc = make_float4(0.f, 0.f, 0.f, 0.f); cur = b;
        }
        float4 v = __ldg((const float4*)x + (size_t)r * 32 + c4);
        acc.x += v.x; acc.y += v.y; acc.z += v.z; acc.w += v.w;
    }
    if (cur >= 0) {
        float* d = &g_S[(size_t)cur * NF + c4 * 4];
        atomicAdd(d + 0, acc.x); atomicAdd(d + 1, acc.y);
        atomicAdd(d + 2, acc.z); atomicAdd(d + 3, acc.w);
    }
}

// ---------------- persistent HMMA GEMM, BM=64, 128 thr, 2 CTAs/SM ----------------
// 4 warps, 1(m)x4(n) grid, warp tile 64x32.  W in registers.  x AND gathered-T
// tiles staged via cp.async one phase ahead; batch indices pipelined TWO phases
// ahead through smem so cp addresses are never LDG-dependent.
// MODE 0: C = Asrc @ W                                  (+ BN0 stats + bn-prep tail)
// MODE 1: C = (x + relu(P[batch]*sc+sh)) @ W + bias     (+ BN1 stats + bn-prep tail)
// MODE 2: C = relu(Asrc*sc + sh) @ W + bias
template <int MODE>
__global__ void __launch_bounds__(128, 2)
gemm_mma(const float* __restrict__ Asrc,
         const uint4* __restrict__ Whi_g, const uint4* __restrict__ Wlo_g,
         const float* __restrict__ bias,
         const float* __restrict__ Tm, const int* __restrict__ batch,
         const float* __restrict__ sc, const float* __restrict__ sh,
         float* __restrict__ C, float* __restrict__ stats,
         const float* __restrict__ gamma, const float* __restrict__ beta,
         float nrows, float* __restrict__ sc_out, float* __restrict__ sh_out,
         unsigned* __restrict__ sync_ctr, int M, int ntiles) {
    constexpr bool STATS = (MODE != 2);
    constexpr bool HASBIAS = (MODE != 0);

    extern __shared__ unsigned char sm[];
    float* psm = (float*)(sm + OFF_PRM);     // sc @128, sh @256 (floats)
    int*   bidx = (int*)(sm + OFF_BIDX);     // [2][64] batch-index pipeline
    const float4* stage  = (const float4*)(sm + OFF_STAGE);
    const float4* stageT = (const float4*)(sm + OFF_STAGET);
    const uint32_t sb = (uint32_t)__cvta_generic_to_shared(sm);

    const int tid = threadIdx.x;
    const int wid = tid >> 5, lane = tid & 31;
    const int tig = lane & 3, grp = lane >> 2;
    const int warp_n = wid;                    // 1x4 grid: warp owns 32-col strip
    const int lrow = lane & 15, lsel = lane >> 4;

    if (MODE != 0 && tid < NF) {
        psm[128 + tid] = __ldg(&sc[tid]);
        psm[256 + tid] = __ldg(&sh[tid]);
    }

    // ---- stage W through the A region, hoist fragments into registers ----
    uint32_t wh[8][2][4], wl[8][2][4];
    {
        uint4* dst = (uint4*)(sm + OFF_AHI);
        for (int i = tid; i < 2176; i += 128) dst[i] = __ldg(&Whi_g[i]);
        __syncthreads();
#pragma unroll
        for (int kt = 0; kt < 8; ++kt)
#pragma unroll
            for (int nb = 0; nb < 2; ++nb) {
                uint32_t a = sb + OFF_AHI + (uint32_t)(kt * 16 + lrow) * 272
                           + (uint32_t)(warp_n * 32 + nb * 16 + lsel * 8) * 2;
                ldsm_x4_t(wh[kt][nb], a);
            }
        __syncthreads();
        for (int i = tid; i < 2176; i += 128) dst[i] = __ldg(&Wlo_g[i]);
        __syncthreads();
#pragma unroll
        for (int kt = 0; kt < 8; ++kt)
#pragma unroll
            for (int nb = 0; nb < 2; ++nb) {
                uint32_t a = sb + OFF_AHI + (uint32_t)(kt * 16 + lrow) * 272
                           + (uint32_t)(warp_n * 32 + nb * 16 + lsel * 8) * 2;
                ldsm_x4_t(wl[kt][nb], a);
            }
        __syncthreads();
    }

    // per-lane BN params for convert (lane <-> float4 column fixed)
    float4 sc4 = make_float4(0.f, 0.f, 0.f, 0.f), sh4 = sc4;
    if (MODE != 0) {
        sc4 = ((const float4*)(psm + 128))[lane];
        sh4 = ((const float4*)(psm + 256))[lane];
    }

    float bias_r[4][2];
#pragma unroll
    for (int nt = 0; nt < 4; ++nt) {
        bias_r[nt][0] = HASBIAS ? __ldg(&bias[warp_n * 32 + nt * 8 + tig * 2]) : 0.f;
        bias_r[nt][1] = HASBIAS ? __ldg(&bias[warp_n * 32 + nt * 8 + tig * 2 + 1]) : 0.f;
    }

    float cs[4][2], cq[4][2];
    if (STATS) {
#pragma unroll
        for (int nt = 0; nt < 4; ++nt) { cs[nt][0] = cs[nt][1] = 0.f; cq[nt][0] = cq[nt][1] = 0.f; }
    }

    unsigned char* Ah = sm + OFF_AHI;
    unsigned char* Al = sm + OFF_ALO;

    // ---- prologue: stage first tile (direct batch LDG, one time) ----
    if (blockIdx.x < ntiles) {
#pragma unroll
        for (int i = 0; i < 16; ++i) {
            int idx = tid + 128 * i;
            int r = idx >> 5, q = idx & 31;
            int rg = blockIdx.x * BM + r;
            int rc = min(rg, M - 1);
            cp16(sb + OFF_STAGE + (uint32_t)(r * 32 + q) * 16,
                 (const float4*)Asrc + (size_t)rc * 32 + q, rg < M ? 16 : 0);
            if (MODE == 1) {
                int g = __ldg(&batch[rc]);
                cp16(sb + OFF_STAGET + (uint32_t)(r * 32 + q) * 16,
                     (const float4*)Tm + (size_t)g * 32 + q, rg < M ? 16 : 0);
            }
        }
    }
    if (MODE == 1 && tid < 64) {
        int nxt = blockIdx.x + gridDim.x;
        int rr = min(nxt * BM + tid, M - 1);
        bidx[tid] = (nxt < ntiles) ? __ldg(&batch[rr]) : 0;
    }
    CP_COMMIT();

    int it = 0;
    for (int tile = blockIdx.x; tile < ntiles; tile += gridDim.x, ++it) {
        CP_WAIT0();
        __syncthreads();   // stage ready; prev mainloop reads of A done; bidx visible

        // ---- convert (pure smem): warp rows [wid*16, wid*16+16) ----
        {
            int crow0 = wid * 16;
#pragma unroll
            for (int i = 0; i < 16; ++i) {
                int crow = crow0 + i;
                int rg = tile * BM + crow;
                bool valid = rg < M;
                float4 v = stage[crow * 32 + lane];
                if (MODE == 1) {
                    float4 t = stageT[crow * 32 + lane];
                    v.x += fmaxf(fmaf(t.x, sc4.x, sh4.x), 0.f);
                    v.y += fmaxf(fmaf(t.y, sc4.y, sh4.y), 0.f);
                    v.z += fmaxf(fmaf(t.z, sc4.z, sh4.z), 0.f);
                    v.w += fmaxf(fmaf(t.w, sc4.w, sh4.w), 0.f);
                } else if (MODE == 2) {
                    v.x = fmaxf(fmaf(v.x, sc4.x, sh4.x), 0.f);
                    v.y = fmaxf(fmaf(v.y, sc4.y, sh4.y), 0.f);
                    v.z = fmaxf(fmaf(v.z, sc4.z, sh4.z), 0.f);
                    v.w = fmaxf(fmaf(v.w, sc4.w, sh4.w), 0.f);
                }
                if (!valid) v = make_float4(0.f, 0.f, 0.f, 0.f);
                uint2 hi, lo;
                split4(v, hi, lo);
                uint32_t off = (uint32_t)crow * 272 + (uint32_t)lane * 8;
                *(uint2*)(Ah + off) = hi;
                *(uint2*)(Al + off) = lo;
            }
        }
        __syncthreads();   // A ready; stages consumed -> safe to refill

        // ---- prefetch next tile (addresses from smem bidx; NO dependent LDGs) ----
        const int p = it & 1;
        const int nxt = tile + gridDim.x;
        int bnext = 0;
        if (MODE == 1 && tid < 64) {
            // kick off batch prefetch for tile nxt+grid (consumed next iteration)
            int nn = nxt + gridDim.x;
            int rr = min(nn * BM + tid, M - 1);
            if (nn < ntiles) bnext = __ldg(&batch[rr]);
        }
        if (nxt < ntiles) {
#pragma unroll
            for (int i = 0; i < 16; ++i) {
                int idx = tid + 128 * i;
                int r = idx >> 5, q = idx & 31;
                int rg = nxt * BM + r;
                int rc = min(rg, M - 1);
                cp16(sb + OFF_STAGE + (uint32_t)(r * 32 + q) * 16,
                     (const float4*)Asrc + (size_t)rc * 32 + q, rg < M ? 16 : 0);
                if (MODE == 1) {
                    int g = bidx[64 * p + r];       // LDS, ready
                    cp16(sb + OFF_STAGET + (uint32_t)(r * 32 + q) * 16,
                         (const float4*)Tm + (size_t)g * 32 + q, rg < M ? 16 : 0);
                }
            }
        }
        CP_COMMIT();

        // ---- HMMA mainloop: 3-chain bf16 split, 64x32 microtile/warp, W in regs ----
        float acc[4][4][4];
#pragma unroll
        for (int mt = 0; mt < 4; ++mt)
#pragma unroll
            for (int nt = 0; nt < 4; ++nt)
#pragma unroll
                for (int e = 0; e < 4; ++e) acc[mt][nt][e] = 0.f;

#pragma unroll
        for (int kt = 0; kt < 8; ++kt) {
            const int k0 = kt * 16;
            uint32_t ahi[4][4], alo[4][4];
#pragma unroll
            for (int mt = 0; mt < 4; ++mt) {
                int r = mt * 16 + lrow;
                uint32_t a = sb + OFF_AHI + (uint32_t)r * 272 + (uint32_t)(k0 + lsel * 8) * 2;
                ldsm_x4(ahi[mt], a);
                ldsm_x4(alo[mt], a + (OFF_ALO - OFF_AHI));
            }
#pragma unroll
            for (int mt = 0; mt < 4; ++mt)
#pragma unroll
                for (int nt = 0; nt < 4; ++nt) {
                    const uint32_t* bh = &wh[kt][nt >> 1][(nt & 1) * 2];
                    const uint32_t* bl = &wl[kt][nt >> 1][(nt & 1) * 2];
                    mma_bf16(acc[mt][nt], ahi[mt], bh);
                    mma_bf16(acc[mt][nt], ahi[mt], bl);
                    mma_bf16(acc[mt][nt], alo[mt], bh);
                }
        }

        // ---- epilogue: bias, store, fused stats ----
#pragma unroll
        for (int mt = 0; mt < 4; ++mt) {
            int r0 = tile * BM + mt * 16 + grp;
            int r1 = r0 + 8;
            bool v0 = r0 < M, v1 = r1 < M;
            float* p0 = C + (size_t)r0 * NF + warp_n * 32 + tig * 2;
            float* p1 = C + (size_t)r1 * NF + warp_n * 32 + tig * 2;
#pragma unroll
            for (int nt = 0; nt < 4; ++nt) {
                float c0 = acc[mt][nt][0] + bias_r[nt][0];
                float c1 = acc[mt][nt][1] + bias_r[nt][1];
                float c2 = acc[mt][nt][2] + bias_r[nt][0];
                float c3 = acc[mt][nt][3] + bias_r[nt][1];
                if (v0) {
                    *(float2*)(p0 + nt * 8) = make_float2(c0, c1);
                    if (STATS) { cs[nt][0] += c0; cs[nt][1] += c1; cq[nt][0] += c0 * c0; cq[nt][1] += c1 * c1; }
                }
                if (v1) {
                    *(float2*)(p1 + nt * 8) = make_float2(c2, c3);
                    if (STATS) { cs[nt][0] += c2; cs[nt][1] += c3; cq[nt][0] += c2 * c2; cq[nt][1] += c3 * c3; }
                }
            }
        }

        // ---- store prefetched batch indices (LDG latency absorbed by mainloop) ----
        if (MODE == 1 && tid < 64) bidx[64 * (p ^ 1) + tid] = bnext;
    }

    // ---- stats flush + last-block bn-prep ----
    if (STATS) {
        CP_WAIT0();
        __syncthreads();
        float* cs_sm = (float*)(sm + OFF_AHI);     // [128]
        float* cq_sm = cs_sm + 128;
#pragma unroll
        for (int nt = 0; nt < 4; ++nt)
#pragma unroll
            for (int par = 0; par < 2; ++par) {
                float s = cs[nt][par], q = cq[nt][par];
#pragma unroll
                for (int msk = 16; msk >= 4; msk >>= 1) {
                    s += __shfl_xor_sync(0xFFFFFFFFu, s, msk);
                    q += __shfl_xor_sync(0xFFFFFFFFu, q, msk);
                }
                if (lane < 4) {
                    int col = warp_n * 32 + nt * 8 + tig * 2 + par;
                    cs_sm[col] = s;
                    cq_sm[col] = q;
                }
            }
        __syncthreads();
        atomicAdd(&stats[tid],      cs_sm[tid]);
        atomicAdd(&stats[NF + tid], cq_sm[tid]);

        __shared__ unsigned last_f;
        __threadfence();
        __syncthreads();
        if (tid == 0) last_f = (atomicAdd(sync_ctr, 1u) == (unsigned)(gridDim.x - 1)) ? 1u : 0u;
        __syncthreads();
        if (last_f) {
            float su = atomicAdd(&stats[tid], 0.f);
            float sq = atomicAdd(&stats[NF + tid], 0.f);
            float mu = su / nrows;
            float var = sq / nrows - mu * mu;
            float s = rsqrtf(var + EPSBN) * __ldg(&gamma[tid]);
            sc_out[tid] = s;
            sh_out[tid] = __ldg(&beta[tid]) - mu * s;
        }
    }
}

// ---------------- launcher ----------------
extern "C" void kernel_launch(void* const* d_in, const int* in_sizes, int n_in,
                              void* d_out, int out_size) {
    const float* x     = (const float*)d_in[0];
    const int*   batch = (const int*)d_in[3];
    const float* W_lin = (const float*)d_in[4];
    const float* bn_g  = (const float*)d_in[5];
    const float* bn_b  = (const float*)d_in[6];
    const float* W1    = (const float*)d_in[7];
    const float* b1    = (const float*)d_in[8];
    const float* bn1_g = (const float*)d_in[9];
    const float* bn1_b = (const float*)d_in[10];
    const float* W2    = (const float*)d_in[11];
    const float* b2    = (const float*)d_in[12];
    float*       out   = (float*)d_out;

    const int M = in_sizes[0] / NF;   // 500000
    const int ntiles_big = (M + BM - 1) / BM;
    const int ntiles_sml = (NGRAPHS + BM - 1) / BM;   // 157

    float *pS, *pP, *pH1, *pstat0, *psc0, *psh0, *pstat1, *psc1, *psh1;
    cudaGetSymbolAddress((void**)&pS, g_S);
    cudaGetSymbolAddress((void**)&pP, g_P);
    cudaGetSymbolAddress((void**)&pH1, g_H1);
    cudaGetSymbolAddress((void**)&pstat0, g_stat0);
    cudaGetSymbolAddress((void**)&psc0, g_sc0);
    cudaGetSymbolAddress((void**)&psh0, g_sh0);
    cudaGetSymbolAddress((void**)&pstat1, g_stat1);
    cudaGetSymbolAddress((void**)&psc1, g_sc1);
    cudaGetSymbolAddress((void**)&psh1, g_sh1);
    unsigned *psync0, *psync1;
    cudaGetSymbolAddress((void**)&psync0, g_sync0);
    cudaGetSymbolAddress((void**)&psync1, g_sync1);
    uint4 *pwlh, *pwll, *pw1h, *pw1l, *pw2h, *pw2l;
    cudaGetSymbolAddress((void**)&pwlh, g_wlhi);
    cudaGetSymbolAddress((void**)&pwll, g_wllo);
    cudaGetSymbolAddress((void**)&pw1h, g_w1hi);
    cudaGetSymbolAddress((void**)&pw1l, g_w1lo);
    cudaGetSymbolAddress((void**)&pw2h, g_w2hi);
    cudaGetSymbolAddress((void**)&pw2l, g_w2lo);

    int dev = 0, nsm = 148;
    cudaGetDevice(&dev);
    cudaDeviceGetAttribute(&nsm, cudaDevAttrMultiProcessorCount, dev);
    const int grid_big = 2 * nsm;
    const int grid_sml = (grid_big < ntiles_sml) ? grid_big : ntiles_sml;

    cudaFuncSetAttribute(gemm_mma<0>, cudaFuncAttributeMaxDynamicSharedMemorySize, SMEM_MMA);
    cudaFuncSetAttribute(gemm_mma<1>, cudaFuncAttributeMaxDynamicSharedMemorySize, SMEM_MMA);
    cudaFuncSetAttribute(gemm_mma<2>, cudaFuncAttributeMaxDynamicSharedMemorySize, SMEM_MMA);

    // (1) init
    init_kernel<<<2500, 256>>>(W_lin, W1, W2);
    // (2) segment sum
    seg_sum_kernel<<<(M + 255) / 256, 128>>>(x, batch, M);
    // (3) P = S @ W_lin  (+ BN0 stats + bn-prep tail)
    gemm_mma<0><<<grid_sml, 128, SMEM_MMA>>>(pS, pwlh, pwll, nullptr, nullptr, nullptr,
                                             nullptr, nullptr, pP, pstat0,
                                             bn_g, bn_b, (float)NGRAPHS, psc0, psh0,
                                             psync0, NGRAPHS, ntiles_sml);
    // (4) H1 = (x + relu(BN0(P))[batch]) @ W1 + b1  (+ BN1 stats + bn-prep tail)
    gemm_mma<1><<<grid_big, 128, SMEM_MMA>>>(x, pw1h, pw1l, b1, pP, batch,
                                             psc0, psh0, pH1, pstat1,
                                             bn1_g, bn1_b, (float)M, psc1, psh1,
                                             psync1, M, ntiles_big);
    // (5) out = relu(BN1(H1)) @ W2 + b2
    gemm_mma<2><<<grid_big, 128, SMEM_MMA>>>(pH1, pw2h, pw2l, b2, nullptr, nullptr,
                                             psc1, psh1, out, nullptr,
                                             nullptr, nullptr, 0.f, nullptr, nullptr,
                                             nullptr, M, ntiles_big);
}

// round 15
// speedup vs baseline: 1.8001x; 1.2401x over previous
#include <cuda_runtime.h>
#include <cuda_bf16.h>
#include <cuda_fp16.h>
#include <cstdint>

// ---------------- problem constants ----------------
#define NF 128
#define NGRAPHS 10000
#define MAXM 500000
#define EPSBN 1e-5f
#define BM 64                       // rows per tile

// ---------------- scratch globals (no allocs allowed) ----------------
__device__ float g_S[NGRAPHS * NF];
__device__ float g_P[NGRAPHS * NF];
__device__ float g_H1[(size_t)MAXM * NF];
__device__ float g_stat0[2 * NF];
__device__ float g_sc0[NF], g_sh0[NF];
__device__ float g_stat1[2 * NF];
__device__ float g_sc1[NF], g_sh1[NF];
__device__ unsigned g_sync0, g_sync1;
// weight tiles, fp16 (hi only), layout [k][n] pitch 136 half (272B/row), 34816B
__device__ uint4 g_wl[2176], g_w1[2176], g_w2[2176];

// ---------------- smem layout ----------------
// x stage 32768 | A hi 17408 | A lo 17408 | params 1536  = 69,120 B -> 2 CTAs/SM
#define OFF_STAGE 0
#define OFF_AHI   32768
#define OFF_ALO   (32768 + 17408)
#define OFF_PRM   (32768 + 34816)
#define SMEM_MMA  (OFF_PRM + 3 * 512)

// ---------------- ptx helpers (sm_80-level only; no tcgen05!) ----------------
__device__ __forceinline__ void ldsm_x4(uint32_t* r, uint32_t addr) {
    asm volatile("ldmatrix.sync.aligned.m8n8.x4.shared.b16 {%0,%1,%2,%3}, [%4];"
                 : "=r"(r[0]), "=r"(r[1]), "=r"(r[2]), "=r"(r[3]) : "r"(addr));
}
__device__ __forceinline__ void ldsm_x4_t(uint32_t* r, uint32_t addr) {
    asm volatile("ldmatrix.sync.aligned.m8n8.x4.trans.shared.b16 {%0,%1,%2,%3}, [%4];"
                 : "=r"(r[0]), "=r"(r[1]), "=r"(r[2]), "=r"(r[3]) : "r"(addr));
}
__device__ __forceinline__ void mma_f16(float* c, const uint32_t* a, const uint32_t* b) {
    asm volatile("mma.sync.aligned.m16n8k16.row.col.f32.f16.f16.f32 "
                 "{%0,%1,%2,%3}, {%4,%5,%6,%7}, {%8,%9}, {%0,%1,%2,%3};"
                 : "+f"(c[0]), "+f"(c[1]), "+f"(c[2]), "+f"(c[3])
                 : "r"(a[0]), "r"(a[1]), "r"(a[2]), "r"(a[3]), "r"(b[0]), "r"(b[1]));
}
__device__ __forceinline__ void cp16(uint32_t dst, const void* src, int sz) {
    asm volatile("cp.async.cg.shared.global [%0], [%1], 16, %2;"
                 :: "r"(dst), "l"(src), "r"(sz));
}
#define CP_COMMIT() asm volatile("cp.async.commit_group;")
#define CP_WAIT0()  asm volatile("cp.async.wait_group 0;")

// fp16 split: hi = rn-fp16 of v (packed), lo = rn-fp16 of residual
__device__ __forceinline__ void split4(float4 v, uint2& hi, uint2& lo) {
    asm("cvt.rn.f16x2.f32 %0, %1, %2;" : "=r"(hi.x) : "f"(v.y), "f"(v.x));
    asm("cvt.rn.f16x2.f32 %0, %1, %2;" : "=r"(hi.y) : "f"(v.w), "f"(v.z));
    __half2 p0 = *reinterpret_cast<__half2*>(&hi.x);
    __half2 p1 = *reinterpret_cast<__half2*>(&hi.y);
    float l0 = v.x - __half2float(__low2half(p0));
    float l1 = v.y - __half2float(__high2half(p0));
    float l2 = v.z - __half2float(__low2half(p1));
    float l3 = v.w - __half2float(__high2half(p1));
    asm("cvt.rn.f16x2.f32 %0, %1, %2;" : "=r"(lo.x) : "f"(l1), "f"(l0));
    asm("cvt.rn.f16x2.f32 %0, %1, %2;" : "=r"(lo.y) : "f"(l3), "f"(l2));
}

// ---------------- init ----------------
__global__ void init_kernel(const float* __restrict__ WL,
                            const float* __restrict__ W1,
                            const float* __restrict__ W2) {
    const int gtid = blockIdx.x * 256 + threadIdx.x;
    const int n1 = NGRAPHS * NF;
    for (int i = gtid; i < n1; i += gridDim.x * 256) g_S[i] = 0.f;
    if (gtid < 2 * NF) { g_stat0[gtid] = 0.f; g_stat1[gtid] = 0.f; }
    if (gtid == 0) { g_sync0 = 0u; g_sync1 = 0u; }
    if (gtid < NF * NF) {
        int k = gtid >> 7, n = gtid & 127;
        uint32_t off = (uint32_t)k * 272 + (uint32_t)n * 2;
        *(unsigned short*)((unsigned char*)g_wl + off) =
            __half_as_ushort(__float2half_rn(WL[gtid]));
        *(unsigned short*)((unsigned char*)g_w1 + off) =
            __half_as_ushort(__float2half_rn(W1[gtid]));
        *(unsigned short*)((unsigned char*)g_w2 + off) =
            __half_as_ushort(__float2half_rn(W2[gtid]));
    }
}

// float4 lanes: 32 threads/row, 4 row-lanes, run-length accumulate per lane
__global__ void seg_sum_kernel(const float* __restrict__ x,
                               const int* __restrict__ batch, int M) {
    const int rg = threadIdx.x >> 5;
    const int c4 = threadIdx.x & 31;
    int r0 = blockIdx.x * 256;
    int rend = min(r0 + 256, M);
    float4 acc = make_float4(0.f, 0.f, 0.f, 0.f);
    int cur = -1;
    for (int r = r0 + rg; r < rend; r += 4) {
        int b = __ldg(&batch[r]);
        if (b != cur) {
            if (cur >= 0) {
                float* d = &g_S[(size_t)cur * NF + c4 * 4];
                atomicAdd(d + 0, acc.x); atomicAdd(d + 1, acc.y);
                atomicAdd(d + 2, acc.z); atomicAdd(d + 3, acc.w);
            }
            acc = make_float4(0.f, 0.f, 0.f, 0.f); cur = b;
        }
        float4 v = __ldg((const float4*)x + (size_t)r * 32 + c4);
        acc.x += v.x; acc.y += v.y; acc.z += v.z; acc.w += v.w;
    }
    if (cur >= 0) {
        float* d = &g_S[(size_t)cur * NF + c4 * 4];
        atomicAdd(d + 0, acc.x); atomicAdd(d + 1, acc.y);
        atomicAdd(d + 2, acc.z); atomicAdd(d + 3, acc.w);
    }
}

// ---------------- persistent HMMA GEMM, BM=64, 128 thr, 2 CTAs/SM ----------------
// 4 warps, 1(m)x4(n) grid, warp tile 64x32.  W (fp16) in registers; 2-chain
// fp16 split (D = Ahi@W + Alo@W).  x tile staged via cp.async one phase ahead.
// MODE 0: C = Asrc @ W                                  (+ BN0 stats + bn-prep tail)
// MODE 1: C = (x + relu(P[batch]*sc+sh)) @ W + bias     (+ BN1 stats + bn-prep tail)
// MODE 2: C = relu(Asrc*sc + sh) @ W + bias
template <int MODE>
__global__ void __launch_bounds__(128, 2)
gemm_mma(const float* __restrict__ Asrc,
         const uint4* __restrict__ W_g,
         const float* __restrict__ bias,
         const float* __restrict__ Tm, const int* __restrict__ batch,
         const float* __restrict__ sc, const float* __restrict__ sh,
         float* __restrict__ C, float* __restrict__ stats,
         const float* __restrict__ gamma, const float* __restrict__ beta,
         float nrows, float* __restrict__ sc_out, float* __restrict__ sh_out,
         unsigned* __restrict__ sync_ctr, int M, int ntiles) {
    constexpr bool STATS = (MODE != 2);
    constexpr bool HASBIAS = (MODE != 0);

    extern __shared__ unsigned char sm[];
    float* psm = (float*)(sm + OFF_PRM);     // sc @128, sh @256 (floats)
    const float4* stage = (const float4*)(sm + OFF_STAGE);
    const uint32_t sb = (uint32_t)__cvta_generic_to_shared(sm);

    const int tid = threadIdx.x;
    const int wid = tid >> 5, lane = tid & 31;
    const int tig = lane & 3, grp = lane >> 2;
    const int warp_n = wid;                    // 1x4 grid: warp owns 32-col strip
    const int lrow = lane & 15, lsel = lane >> 4;

    if (MODE != 0 && tid < NF) {
        psm[128 + tid] = __ldg(&sc[tid]);
        psm[256 + tid] = __ldg(&sh[tid]);
    }

    // ---- stage W through the A region, hoist fragments into registers ----
    uint32_t wh[8][2][4];
    {
        uint4* dst = (uint4*)(sm + OFF_AHI);   // 34816 B = full W tile
        for (int i = tid; i < 2176; i += 128) dst[i] = __ldg(&W_g[i]);
        __syncthreads();
#pragma unroll
        for (int kt = 0; kt < 8; ++kt)
#pragma unroll
            for (int nb = 0; nb < 2; ++nb) {
                uint32_t a = sb + OFF_AHI + (uint32_t)(kt * 16 + lrow) * 272
                           + (uint32_t)(warp_n * 32 + nb * 16 + lsel * 8) * 2;
                ldsm_x4_t(wh[kt][nb], a);
            }
        __syncthreads();
    }

    // per-lane BN params for convert (lane <-> float4 column fixed)
    float4 sc4 = make_float4(0.f, 0.f, 0.f, 0.f), sh4 = sc4;
    if (MODE != 0) {
        sc4 = ((const float4*)(psm + 128))[lane];
        sh4 = ((const float4*)(psm + 256))[lane];
    }

    float bias_r[4][2];
#pragma unroll
    for (int nt = 0; nt < 4; ++nt) {
        bias_r[nt][0] = HASBIAS ? __ldg(&bias[warp_n * 32 + nt * 8 + tig * 2]) : 0.f;
        bias_r[nt][1] = HASBIAS ? __ldg(&bias[warp_n * 32 + nt * 8 + tig * 2 + 1]) : 0.f;
    }

    float cs[4][2], cq[4][2];
    if (STATS) {
#pragma unroll
        for (int nt = 0; nt < 4; ++nt) { cs[nt][0] = cs[nt][1] = 0.f; cq[nt][0] = cq[nt][1] = 0.f; }
    }

    unsigned char* Ah = sm + OFF_AHI;
    unsigned char* Al = sm + OFF_ALO;

    // ---- prologue: stage first tile ----
    if (blockIdx.x < ntiles) {
#pragma unroll
        for (int i = 0; i < 16; ++i) {
            int idx = tid + 128 * i;
            int r = idx >> 5, q = idx & 31;
            int rg = blockIdx.x * BM + r;
            cp16(sb + OFF_STAGE + (uint32_t)(r * 32 + q) * 16,
                 (const float4*)Asrc + (size_t)min(rg, M - 1) * 32 + q,
                 rg < M ? 16 : 0);
        }
    }
    CP_COMMIT();

    for (int tile = blockIdx.x; tile < ntiles; tile += gridDim.x) {
        CP_WAIT0();
        __syncthreads();   // stage ready; previous mainloop reads of A complete

        // ---- convert: warp rows [wid*16, wid*16+16), lane = float4 col ----
        {
            int crow0 = wid * 16;
            float4 tc = make_float4(0.f, 0.f, 0.f, 0.f), tn = tc;
            if (MODE == 1) {
                int rc = min(tile * BM + crow0, M - 1);
                tc = __ldg((const float4*)(Tm + (size_t)__ldg(&batch[rc]) * NF) + lane);
            }
#pragma unroll
            for (int i = 0; i < 16; ++i) {
                int crow = crow0 + i;
                int rg = tile * BM + crow;
                bool valid = rg < M;
                if (MODE == 1 && i < 15) {
                    int rc = min(rg + 1, M - 1);
                    tn = __ldg((const float4*)(Tm + (size_t)__ldg(&batch[rc]) * NF) + lane);
                }
                float4 v = stage[crow * 32 + lane];
                if (MODE == 1) {
                    v.x += fmaxf(fmaf(tc.x, sc4.x, sh4.x), 0.f);
                    v.y += fmaxf(fmaf(tc.y, sc4.y, sh4.y), 0.f);
                    v.z += fmaxf(fmaf(tc.z, sc4.z, sh4.z), 0.f);
                    v.w += fmaxf(fmaf(tc.w, sc4.w, sh4.w), 0.f);
                } else if (MODE == 2) {
                    v.x = fmaxf(fmaf(v.x, sc4.x, sh4.x), 0.f);
                    v.y = fmaxf(fmaf(v.y, sc4.y, sh4.y), 0.f);
                    v.z = fmaxf(fmaf(v.z, sc4.z, sh4.z), 0.f);
                    v.w = fmaxf(fmaf(v.w, sc4.w, sh4.w), 0.f);
                }
                if (!valid) v = make_float4(0.f, 0.f, 0.f, 0.f);
                uint2 hi, lo;
                split4(v, hi, lo);
                uint32_t off = (uint32_t)crow * 272 + (uint32_t)lane * 8;
                *(uint2*)(Ah + off) = hi;
                *(uint2*)(Al + off) = lo;
                tc = tn;
            }
        }
        __syncthreads();   // A ready; stage consumed -> safe to refill

        // ---- prefetch next tile into stage (overlaps with mainloop) ----
        {
            int nxt = tile + gridDim.x;
            if (nxt < ntiles) {
#pragma unroll
                for (int i = 0; i < 16; ++i) {
                    int idx = tid + 128 * i;
                    int r = idx >> 5, q = idx & 31;
                    int rg = nxt * BM + r;
                    cp16(sb + OFF_STAGE + (uint32_t)(r * 32 + q) * 16,
                         (const float4*)Asrc + (size_t)min(rg, M - 1) * 32 + q,
                         rg < M ? 16 : 0);
                }
            }
            CP_COMMIT();
        }

        // ---- HMMA mainloop: 2-chain fp16 split, 64x32 microtile/warp, W in regs ----
        float acc[4][4][4];
#pragma unroll
        for (int mt = 0; mt < 4; ++mt)
#pragma unroll
            for (int nt = 0; nt < 4; ++nt)
#pragma unroll
                for (int e = 0; e < 4; ++e) acc[mt][nt][e] = 0.f;

#pragma unroll
        for (int kt = 0; kt < 8; ++kt) {
            const int k0 = kt * 16;
            uint32_t ahi[4][4], alo[4][4];
#pragma unroll
            for (int mt = 0; mt < 4; ++mt) {
                int r = mt * 16 + lrow;
                uint32_t a = sb + OFF_AHI + (uint32_t)r * 272 + (uint32_t)(k0 + lsel * 8) * 2;
                ldsm_x4(ahi[mt], a);
                ldsm_x4(alo[mt], a + (OFF_ALO - OFF_AHI));
            }
#pragma unroll
            for (int mt = 0; mt < 4; ++mt)
#pragma unroll
                for (int nt = 0; nt < 4; ++nt) {
                    const uint32_t* bh = &wh[kt][nt >> 1][(nt & 1) * 2];
                    mma_f16(acc[mt][nt], ahi[mt], bh);
                    mma_f16(acc[mt][nt], alo[mt], bh);
                }
        }

        // ---- epilogue: bias, store, fused stats ----
#pragma unroll
        for (int mt = 0; mt < 4; ++mt) {
            int r0 = tile * BM + mt * 16 + grp;
            int r1 = r0 + 8;
            bool v0 = r0 < M, v1 = r1 < M;
            float* p0 = C + (size_t)r0 * NF + warp_n * 32 + tig * 2;
            float* p1 = C + (size_t)r1 * NF + warp_n * 32 + tig * 2;
#pragma unroll
            for (int nt = 0; nt < 4; ++nt) {
                float c0 = acc[mt][nt][0] + bias_r[nt][0];
                float c1 = acc[mt][nt][1] + bias_r[nt][1];
                float c2 = acc[mt][nt][2] + bias_r[nt][0];
                float c3 = acc[mt][nt][3] + bias_r[nt][1];
                if (v0) {
                    *(float2*)(p0 + nt * 8) = make_float2(c0, c1);
                    if (STATS) { cs[nt][0] += c0; cs[nt][1] += c1; cq[nt][0] += c0 * c0; cq[nt][1] += c1 * c1; }
                }
                if (v1) {
                    *(float2*)(p1 + nt * 8) = make_float2(c2, c3);
                    if (STATS) { cs[nt][0] += c2; cs[nt][1] += c3; cq[nt][0] += c2 * c2; cq[nt][1] += c3 * c3; }
                }
            }
        }
    }

    // ---- stats flush + last-block bn-prep ----
    if (STATS) {
        CP_WAIT0();
        __syncthreads();
        float* cs_sm = (float*)(sm + OFF_AHI);     // [128]
        float* cq_sm = cs_sm + 128;
#pragma unroll
        for (int nt = 0; nt < 4; ++nt)
#pragma unroll
            for (int par = 0; par < 2; ++par) {
                float s = cs[nt][par], q = cq[nt][par];
#pragma unroll
                for (int msk = 16; msk >= 4; msk >>= 1) {
                    s += __shfl_xor_sync(0xFFFFFFFFu, s, msk);
                    q += __shfl_xor_sync(0xFFFFFFFFu, q, msk);
                }
                if (lane < 4) {
                    int col = warp_n * 32 + nt * 8 + tig * 2 + par;
                    cs_sm[col] = s;
                    cq_sm[col] = q;
                }
            }
        __syncthreads();
        atomicAdd(&stats[tid],      cs_sm[tid]);
        atomicAdd(&stats[NF + tid], cq_sm[tid]);

        __shared__ unsigned last_f;
        __threadfence();
        __syncthreads();
        if (tid == 0) last_f = (atomicAdd(sync_ctr, 1u) == (unsigned)(gridDim.x - 1)) ? 1u : 0u;
        __syncthreads();
        if (last_f) {
            float su = atomicAdd(&stats[tid], 0.f);
            float sq = atomicAdd(&stats[NF + tid], 0.f);
            float mu = su / nrows;
            float var = sq / nrows - mu * mu;
            float s = rsqrtf(var + EPSBN) * __ldg(&gamma[tid]);
            sc_out[tid] = s;
            sh_out[tid] = __ldg(&beta[tid]) - mu * s;
        }
    }
}

// ---------------- launcher ----------------
extern "C" void kernel_launch(void* const* d_in, const int* in_sizes, int n_in,
                              void* d_out, int out_size) {
    const float* x     = (const float*)d_in[0];
    const int*   batch = (const int*)d_in[3];
    const float* W_lin = (const float*)d_in[4];
    const float* bn_g  = (const float*)d_in[5];
    const float* bn_b  = (const float*)d_in[6];
    const float* W1    = (const float*)d_in[7];
    const float* b1    = (const float*)d_in[8];
    const float* bn1_g = (const float*)d_in[9];
    const float* bn1_b = (const float*)d_in[10];
    const float* W2    = (const float*)d_in[11];
    const float* b2    = (const float*)d_in[12];
    float*       out   = (float*)d_out;

    const int M = in_sizes[0] / NF;   // 500000
    const int ntiles_big = (M + BM - 1) / BM;
    const int ntiles_sml = (NGRAPHS + BM - 1) / BM;   // 157

    float *pS, *pP, *pH1, *pstat0, *psc0, *psh0, *pstat1, *psc1, *psh1;
    cudaGetSymbolAddress((void**)&pS, g_S);
    cudaGetSymbolAddress((void**)&pP, g_P);
    cudaGetSymbolAddress((void**)&pH1, g_H1);
    cudaGetSymbolAddress((void**)&pstat0, g_stat0);
    cudaGetSymbolAddress((void**)&psc0, g_sc0);
    cudaGetSymbolAddress((void**)&psh0, g_sh0);
    cudaGetSymbolAddress((void**)&pstat1, g_stat1);
    cudaGetSymbolAddress((void**)&psc1, g_sc1);
    cudaGetSymbolAddress((void**)&psh1, g_sh1);
    unsigned *psync0, *psync1;
    cudaGetSymbolAddress((void**)&psync0, g_sync0);
    cudaGetSymbolAddress((void**)&psync1, g_sync1);
    uint4 *pwl, *pw1, *pw2;
    cudaGetSymbolAddress((void**)&pwl, g_wl);
    cudaGetSymbolAddress((void**)&pw1, g_w1);
    cudaGetSymbolAddress((void**)&pw2, g_w2);

    int dev = 0, nsm = 148;
    cudaGetDevice(&dev);
    cudaDeviceGetAttribute(&nsm, cudaDevAttrMultiProcessorCount, dev);
    const int grid_big = 2 * nsm;
    const int grid_sml = (grid_big < ntiles_sml) ? grid_big : ntiles_sml;

    cudaFuncSetAttribute(gemm_mma<0>, cudaFuncAttributeMaxDynamicSharedMemorySize, SMEM_MMA);
    cudaFuncSetAttribute(gemm_mma<1>, cudaFuncAttributeMaxDynamicSharedMemorySize, SMEM_MMA);
    cudaFuncSetAttribute(gemm_mma<2>, cudaFuncAttributeMaxDynamicSharedMemorySize, SMEM_MMA);

    // (1) init
    init_kernel<<<2500, 256>>>(W_lin, W1, W2);
    // (2) segment sum
    seg_sum_kernel<<<(M + 255) / 256, 128>>>(x, batch, M);
    // (3) P = S @ W_lin  (+ BN0 stats + bn-prep tail)
    gemm_mma<0><<<grid_sml, 128, SMEM_MMA>>>(pS, pwl, nullptr, nullptr, nullptr,
                                             nullptr, nullptr, pP, pstat0,
                                             bn_g, bn_b, (float)NGRAPHS, psc0, psh0,
                                             psync0, NGRAPHS, ntiles_sml);
    // (4) H1 = (x + relu(BN0(P))[batch]) @ W1 + b1  (+ BN1 stats + bn-prep tail)
    gemm_mma<1><<<grid_big, 128, SMEM_MMA>>>(x, pw1, b1, pP, batch,
                                             psc0, psh0, pH1, pstat1,
                                             bn1_g, bn1_b, (float)M, psc1, psh1,
                                             psync1, M, ntiles_big);
    // (5) out = relu(BN1(H1)) @ W2 + b2
    gemm_mma<2><<<grid_big, 128, SMEM_MMA>>>(pH1, pw2, b2, nullptr, nullptr,
                                             psc1, psh1, out, nullptr,
                                             nullptr, nullptr, 0.f, nullptr, nullptr,
                                             nullptr, M, ntiles_big);
}